// round 13
// baseline (speedup 1.0000x reference)
#include <cuda_runtime.h>
#include <math.h>

#define NB 1024
#define TE 168
#define TD 24
#define NF 64
#define NH 128

typedef unsigned long long u64;

// ---- globals ----
__device__ float2 g_midp[(NB/2) * TE * NH];
__device__ float  g_wx  [NB * TE * NH];
__device__ float2 g_hmp [(NB/2) * NH];
__device__ float2 g_cmp [(NB/2) * NH];

// row-pair (k-major float4) weights for t1/s/q/wx stages
__device__ float4 gT4_We [64 * 128];
__device__ float4 gT4_Wi [16 * 128];
__device__ float4 gT4_Vd [32 * 64];
__device__ float4 gT4_Wh [64 * 128];
__device__ float4 gT4_Wx [32 * 128];
// col-pair packed gate weights: gP[kb*256 + cp] = { {W[2cp][2kb],W[2cp+1][2kb]}, {W[2cp][2kb+1],W[2cp+1][2kb+1]} }
__device__ ulonglong2 gP_eWih[32 * 256];
__device__ ulonglong2 gP_eWhh[64 * 256];
__device__ ulonglong2 gP_mWih[64 * 256];
__device__ ulonglong2 gP_mWhh[64 * 256];
__device__ ulonglong2 gP_dWih[64 * 256];
__device__ ulonglong2 gP_dWhh[64 * 256];

__device__ __forceinline__ float ftanh(float x) {
    x = fminf(15.0f, fmaxf(-15.0f, x));
    const float e = __expf(2.0f * x);
    return __fdividef(e - 1.0f, e + 1.0f);
}
__device__ __forceinline__ float fsigm(float x) {
    return __fdividef(1.0f, 1.0f + __expf(-x));
}
__device__ __forceinline__ u64 dup2(float x) {
    u64 r; asm("mov.b64 %0, {%1, %1};" : "=l"(r) : "f"(x)); return r;
}
__device__ __forceinline__ u64 pkf2(float a, float b) {
    u64 r; asm("mov.b64 %0, {%1, %2};" : "=l"(r) : "f"(a), "f"(b)); return r;
}
__device__ __forceinline__ float2 unp2(u64 v) {
    float2 r; asm("mov.b64 {%0, %1}, %2;" : "=f"(r.x), "=f"(r.y) : "l"(v)); return r;
}
__device__ __forceinline__ void ffma2(u64& d, u64 a, u64 b) {
    asm("fma.rn.f32x2 %0, %1, %2, %0;" : "+l"(d) : "l"(a), "l"(b));
}

// row-pair micro-op (t1/s/q/wx stages)
__device__ __forceinline__ void gemm_kg(u64& acc, const float4 w,
                                        const ulonglong2* __restrict__ act, int kg)
{
    const u64 w0 = dup2(w.x), w1 = dup2(w.y), w2 = dup2(w.z), w3 = dup2(w.w);
    const ulonglong2 a01 = act[2 * kg];
    const ulonglong2 a23 = act[2 * kg + 1];
    ffma2(acc, w0, a01.x); ffma2(acc, w1, a01.y);
    ffma2(acc, w2, a23.x); ffma2(acc, w3, a23.y);
}
// col-pair micro-op (gate stages): wv = col-pair weights for k=2kb,2kb+1; ad = dup'd acts
#define GKB(A, wv, ad, kb) do { \
    const ulonglong2 _a = (ad)[kb]; \
    ffma2(A, (wv).x, _a.x); ffma2(A, (wv).y, _a.y); } while (0)

// ---------------- Kernel 0: pack weights ----------------
__device__ __forceinline__ void packW4(const float* __restrict__ W, float4* dst,
                                       int C, int K, int i0, int st)
{
    const int n = C * (K >> 2);
    for (int i = i0; i < n; i += st) {
        const int c = i % C, kg = i / C;
        const float* p = W + c * K + kg * 4;
        dst[i] = make_float4(p[0], p[1], p[2], p[3]);
    }
}
__device__ __forceinline__ void packP(const float* __restrict__ W, ulonglong2* dst,
                                      int C, int K, int i0, int st)
{
    const int n = (C >> 1) * (K >> 1);
    const int CP = C >> 1;
    for (int i = i0; i < n; i += st) {
        const int cp = i % CP, kb = i / CP;
        const float* r0 = W + (2 * cp) * K + 2 * kb;
        const float* r1 = W + (2 * cp + 1) * K + 2 * kb;
        ulonglong2 v;
        v.x = pkf2(r0[0], r1[0]);
        v.y = pkf2(r0[1], r1[1]);
        dst[i] = v;
    }
}

__global__ void k_tr(const float* __restrict__ eWih, const float* __restrict__ eWhh,
                     const float* __restrict__ mWih, const float* __restrict__ mWhh,
                     const float* __restrict__ dWih, const float* __restrict__ dWhh,
                     const float* __restrict__ We,   const float* __restrict__ Wi,
                     const float* __restrict__ Vd,   const float* __restrict__ Wh,
                     const float* __restrict__ Wx)
{
    const int i0 = blockIdx.x * blockDim.x + threadIdx.x;
    const int st = gridDim.x * blockDim.x;
    packP(eWih, gP_eWih, 512, 64,  i0, st);
    packP(eWhh, gP_eWhh, 512, 128, i0, st);
    packP(mWih, gP_mWih, 512, 128, i0, st);
    packP(mWhh, gP_mWhh, 512, 128, i0, st);
    packP(dWih, gP_dWih, 512, 128, i0, st);
    packP(dWhh, gP_dWhh, 512, 128, i0, st);
    packW4(We,  gT4_We,  128, 256, i0, st);
    packW4(Wi,  gT4_Wi,  128, 64,  i0, st);
    packW4(Vd,  gT4_Vd,  64,  128, i0, st);
    packW4(Wh,  gT4_Wh,  128, 256, i0, st);
    packW4(Wx,  gT4_Wx,  128, 128, i0, st);
}

// ---------------- Kernel 1: encoder + mid LSTM ----------------
__global__ __launch_bounds__(512, 2)
void k_enc_mid(const float* __restrict__ X,
               const float* __restrict__ Wi_b, const float* __restrict__ Vd_b,
               const float* __restrict__ ebih, const float* __restrict__ ebhh,
               const float* __restrict__ mbih, const float* __restrict__ mbhh)
{
    __shared__ __align__(16) float2 hcp [2][256];   // enc [h|c] paired
    __shared__ __align__(16) u64    hdup[4][128];   // enc h duplicated
    __shared__ __align__(16) u64    hmdup[4][128];  // mid h duplicated
    __shared__ __align__(16) float2 cmp2[2][128];   // mid c paired
    __shared__ __align__(16) float2 xtp [2][64];
    __shared__ __align__(16) u64    xind[4][64];    // x_in duplicated
    __shared__ __align__(16) float2 t1p [2][128];
    __shared__ __align__(16) float2 scrA[768];
    __shared__ __align__(16) u64    scrG[2][256][4];

    const int tid = threadIdx.x;
    const int r0  = blockIdx.x * 4;
    const int p0  = blockIdx.x * 2;
    const int wno = tid >> 5, lane = tid & 31;

    {
        const int rp = tid >> 8, k = tid & 255;
        hcp[rp][k] = make_float2(0.f, 0.f);
        hdup[tid >> 7][tid & 127]  = 0ull;
        hmdup[tid >> 7][tid & 127] = 0ull;
        if (tid < 256) cmp2[tid >> 7][tid & 127] = make_float2(0.f, 0.f);
    }
    __syncthreads();

    for (int t = 0; t < TE; ++t) {
        if (tid < 256) {
            const int f = tid & 63, rp = (tid >> 6) & 1, half = tid >> 7;
            ((float*)&xtp[rp][f])[half] = X[((r0 + 2 * rp + half) * TE + t) * NF + f];
        }
        __syncthreads();

        // t1 partials (row-pair lanes, k-split)
        {
            const int j = tid & 127, rp = (tid >> 7) & 1, half = tid >> 8;
            const ulonglong2* hp = (const ulonglong2*)hcp[rp];
            u64 acc;
            if (!half) {
                acc = dup2(Wi_b[j]);
                #pragma unroll 8
                for (int kg = 0; kg < 40; ++kg)
                    gemm_kg(acc, gT4_We[kg * 128 + j], hp, kg);
            } else {
                acc = 0ull;
                #pragma unroll 8
                for (int kg = 40; kg < 64; ++kg)
                    gemm_kg(acc, gT4_We[kg * 128 + j], hp, kg);
                const ulonglong2* xp = (const ulonglong2*)xtp[rp];
                #pragma unroll
                for (int kg = 0; kg < 16; ++kg)
                    gemm_kg(acc, gT4_Wi[kg * 128 + j], xp, kg);
            }
            scrA[half * 256 + rp * 128 + j] = unp2(acc);
        }
        __syncthreads();

        if (tid < 256) {
            const int j = tid & 127, rp = tid >> 7;
            const float2 a = scrA[rp * 128 + j], b = scrA[256 + rp * 128 + j];
            t1p[rp][j] = make_float2(ftanh(a.x + b.x), ftanh(a.y + b.y));
        }
        __syncthreads();

        // s partials
        if (tid < 256) {
            const int f = tid & 63, rp = (tid >> 6) & 1, half = tid >> 7;
            u64 acc = half ? 0ull : dup2(Vd_b[f]);
            const ulonglong2* tp = (const ulonglong2*)t1p[rp];
            const int k0 = half * 16;
            #pragma unroll 8
            for (int kg = k0; kg < k0 + 16; ++kg)
                gemm_kg(acc, gT4_Vd[kg * 64 + f], tp, kg);
            scrA[512 + half * 128 + rp * 64 + f] = unp2(acc);
        }
        __syncthreads();

        // softmax + x_in (dup store)
        if (wno < 4) {
            const int rp = wno >> 1, rh = wno & 1;
            const float2 a0 = scrA[512 + rp * 64 + lane];
            const float2 b0 = scrA[640 + rp * 64 + lane];
            const float2 a1 = scrA[512 + rp * 64 + lane + 32];
            const float2 b1 = scrA[640 + rp * 64 + lane + 32];
            float v0 = rh ? (a0.y + b0.y) : (a0.x + b0.x);
            float v1 = rh ? (a1.y + b1.y) : (a1.x + b1.x);
            float mx = fmaxf(v0, v1);
            #pragma unroll
            for (int o = 16; o; o >>= 1) mx = fmaxf(mx, __shfl_xor_sync(~0u, mx, o));
            float e0 = __expf(v0 - mx), e1 = __expf(v1 - mx);
            float sm = e0 + e1;
            #pragma unroll
            for (int o = 16; o; o >>= 1) sm += __shfl_xor_sync(~0u, sm, o);
            const float inv = __fdividef(1.0f, sm);
            const int row = 2 * rp + rh;
            const float2 x0 = xtp[rp][lane], x1 = xtp[rp][lane + 32];
            const float xi0 = (rh ? x0.y : x0.x) * e0 * inv;
            const float xi1 = (rh ? x1.y : x1.x) * e1 * inv;
            xind[row][lane]      = dup2(xi0);
            xind[row][lane + 32] = dup2(xi1);
        }
        __syncthreads();

        // enc gates (col-pair lanes, k-split)
        {
            const int cp = tid & 255, half = tid >> 8;
            u64 A0, A1, A2, A3;
            if (!half) {
                const float2 bi = ((const float2*)ebih)[cp];
                const float2 bh = ((const float2*)ebhh)[cp];
                A0 = pkf2(bi.x + bh.x, bi.y + bh.y);
            } else A0 = 0ull;
            A1 = A0; A2 = A0; A3 = A0;
            const ulonglong2* h0 = (const ulonglong2*)hdup[0];
            const ulonglong2* h1 = (const ulonglong2*)hdup[1];
            const ulonglong2* h2 = (const ulonglong2*)hdup[2];
            const ulonglong2* h3 = (const ulonglong2*)hdup[3];
            if (!half) {
                const ulonglong2* x0 = (const ulonglong2*)xind[0];
                const ulonglong2* x1 = (const ulonglong2*)xind[1];
                const ulonglong2* x2 = (const ulonglong2*)xind[2];
                const ulonglong2* x3 = (const ulonglong2*)xind[3];
                #pragma unroll 8
                for (int kb = 0; kb < 32; ++kb) {
                    const ulonglong2 wv = gP_eWih[kb * 256 + cp];
                    GKB(A0, wv, x0, kb); GKB(A1, wv, x1, kb);
                    GKB(A2, wv, x2, kb); GKB(A3, wv, x3, kb);
                }
                #pragma unroll 8
                for (int kb = 0; kb < 16; ++kb) {
                    const ulonglong2 wv = gP_eWhh[kb * 256 + cp];
                    GKB(A0, wv, h0, kb); GKB(A1, wv, h1, kb);
                    GKB(A2, wv, h2, kb); GKB(A3, wv, h3, kb);
                }
            } else {
                #pragma unroll 8
                for (int kb = 16; kb < 64; ++kb) {
                    const ulonglong2 wv = gP_eWhh[kb * 256 + cp];
                    GKB(A0, wv, h0, kb); GKB(A1, wv, h1, kb);
                    GKB(A2, wv, h2, kb); GKB(A3, wv, h3, kb);
                }
            }
            scrG[half][cp][0] = A0; scrG[half][cp][1] = A1;
            scrG[half][cp][2] = A2; scrG[half][cp][3] = A3;
        }
        __syncthreads();

        // enc LSTM update
        {
            const int j = tid & 127, r = tid >> 7;
            const int jc = j >> 1, jl = j & 1;
            const float gi = ((const float*)&scrG[0][jc      ][r])[jl] + ((const float*)&scrG[1][jc      ][r])[jl];
            const float gf = ((const float*)&scrG[0][jc +  64][r])[jl] + ((const float*)&scrG[1][jc +  64][r])[jl];
            const float gg = ((const float*)&scrG[0][jc + 128][r])[jl] + ((const float*)&scrG[1][jc + 128][r])[jl];
            const float go = ((const float*)&scrG[0][jc + 192][r])[jl] + ((const float*)&scrG[1][jc + 192][r])[jl];
            const float co = ((const float*)&hcp[r >> 1][128 + j])[r & 1];
            const float cn = fsigm(gf) * co + fsigm(gi) * ftanh(gg);
            const float hn = fsigm(go) * ftanh(cn);
            ((float*)&hcp[r >> 1][j])[r & 1]       = hn;
            ((float*)&hcp[r >> 1][128 + j])[r & 1] = cn;
            hdup[r][j] = dup2(hn);
        }
        __syncthreads();

        // mid gates (col-pair lanes, k-split: half0 = Wih on h, half1 = Whh on hm)
        {
            const int cp = tid & 255, half = tid >> 8;
            u64 A0, A1, A2, A3;
            if (!half) {
                const float2 bi = ((const float2*)mbih)[cp];
                const float2 bh = ((const float2*)mbhh)[cp];
                A0 = pkf2(bi.x + bh.x, bi.y + bh.y);
            } else A0 = 0ull;
            A1 = A0; A2 = A0; A3 = A0;
            if (!half) {
                const ulonglong2* h0 = (const ulonglong2*)hdup[0];
                const ulonglong2* h1 = (const ulonglong2*)hdup[1];
                const ulonglong2* h2 = (const ulonglong2*)hdup[2];
                const ulonglong2* h3 = (const ulonglong2*)hdup[3];
                #pragma unroll 8
                for (int kb = 0; kb < 64; ++kb) {
                    const ulonglong2 wv = gP_mWih[kb * 256 + cp];
                    GKB(A0, wv, h0, kb); GKB(A1, wv, h1, kb);
                    GKB(A2, wv, h2, kb); GKB(A3, wv, h3, kb);
                }
            } else {
                const ulonglong2* m0 = (const ulonglong2*)hmdup[0];
                const ulonglong2* m1 = (const ulonglong2*)hmdup[1];
                const ulonglong2* m2 = (const ulonglong2*)hmdup[2];
                const ulonglong2* m3 = (const ulonglong2*)hmdup[3];
                #pragma unroll 8
                for (int kb = 0; kb < 64; ++kb) {
                    const ulonglong2 wv = gP_mWhh[kb * 256 + cp];
                    GKB(A0, wv, m0, kb); GKB(A1, wv, m1, kb);
                    GKB(A2, wv, m2, kb); GKB(A3, wv, m3, kb);
                }
            }
            scrG[half][cp][0] = A0; scrG[half][cp][1] = A1;
            scrG[half][cp][2] = A2; scrG[half][cp][3] = A3;
        }
        __syncthreads();

        // mid LSTM update + g_mid store
        {
            const int j = tid & 127, r = tid >> 7;
            const int jc = j >> 1, jl = j & 1;
            const float gi = ((const float*)&scrG[0][jc      ][r])[jl] + ((const float*)&scrG[1][jc      ][r])[jl];
            const float gf = ((const float*)&scrG[0][jc +  64][r])[jl] + ((const float*)&scrG[1][jc +  64][r])[jl];
            const float gg = ((const float*)&scrG[0][jc + 128][r])[jl] + ((const float*)&scrG[1][jc + 128][r])[jl];
            const float go = ((const float*)&scrG[0][jc + 192][r])[jl] + ((const float*)&scrG[1][jc + 192][r])[jl];
            const float co = ((const float*)&cmp2[r >> 1][j])[r & 1];
            const float cn = fsigm(gf) * co + fsigm(gi) * ftanh(gg);
            const float hn = fsigm(go) * ftanh(cn);
            ((float*)&cmp2[r >> 1][j])[r & 1] = cn;
            hmdup[r][j] = dup2(hn);
            ((float*)&g_midp[((p0 + (r >> 1)) * TE + t) * NH + j])[r & 1] = hn;
        }
        __syncthreads();
    }

    if (tid < 256) {
        const int j = tid & 127, rp = tid >> 7;
        g_hmp[(p0 + rp) * NH + j] = make_float2(unp2(hmdup[2 * rp][j]).x,
                                                unp2(hmdup[2 * rp + 1][j]).x);
        g_cmp[(p0 + rp) * NH + j] = cmp2[rp][j];
    }
}

// ---------------- Kernel 2: wx_mid ----------------
__global__ __launch_bounds__(256, 1)
void k_wx(const float* __restrict__ Wx_b)
{
    __shared__ __align__(16) float2 msp[16][128];
    const int tid = threadIdx.x;
    const int ub  = blockIdx.x * 16;

    for (int i = tid; i < 16 * 128; i += 256)
        msp[i >> 7][i & 127] = g_midp[ub * NH + i];
    __syncthreads();

    const int j = tid & 127, rg = tid >> 7;
    const u64 bini = dup2(Wx_b[j]);
    u64 acc[8];
    #pragma unroll
    for (int u = 0; u < 8; ++u) acc[u] = bini;

    #pragma unroll 4
    for (int kg = 0; kg < 32; ++kg) {
        const float4 w = gT4_Wx[kg * 128 + j];
        #pragma unroll
        for (int u = 0; u < 8; ++u)
            gemm_kg(acc[u], w, (const ulonglong2*)msp[rg * 8 + u], kg);
    }
    #pragma unroll
    for (int u = 0; u < 8; ++u) {
        const int gu = ub + rg * 8 + u;
        const int pair = gu / TE, tt = gu % TE;
        const float2 r = unp2(acc[u]);
        g_wx[((2 * pair)     * TE + tt) * NH + j] = r.x;
        g_wx[((2 * pair + 1) * TE + tt) * NH + j] = r.y;
    }
}

// ---------------- Kernel 3: decoder ----------------
__global__ __launch_bounds__(512, 2)
void k_dec(const float* __restrict__ V_w,  const float* __restrict__ V_b,
           const float* __restrict__ dbih, const float* __restrict__ dbhh,
           const float* __restrict__ regw, const float* __restrict__ regb,
           float* __restrict__ out)
{
    __shared__ __align__(16) float2 hicp[2][256];
    __shared__ __align__(16) u64    hicd[4][128];
    __shared__ __align__(16) float2 qsp [2][128];
    __shared__ __align__(16) float2 ssp2[2][TE];
    __shared__ __align__(16) u64    dind[4][128];
    __shared__ __align__(16) float2 scrA[512];
    __shared__ __align__(16) u64    scrG[2][256][4];

    const int tid = threadIdx.x;
    const int r0  = blockIdx.x * 4;
    const int p0  = blockIdx.x * 2;
    const int wno = tid >> 5, lane = tid & 31;

    const float4 vw4 = ((const float4*)V_w)[lane];
    const float  vb  = V_b[0];

    {
        const int rp = tid >> 8, k = tid & 255;
        hicp[rp][k] = (k < 128) ? g_hmp[(p0 + rp) * NH + k]
                                : g_cmp[(p0 + rp) * NH + (k - 128)];
        const int j = tid & 127, r = tid >> 7;
        const float2 p = g_hmp[(p0 + (r >> 1)) * NH + j];
        hicd[r][j] = dup2((r & 1) ? p.y : p.x);
    }
    __syncthreads();

    for (int td = 0; td < TD; ++td) {
        // q partials (row-pair lanes, k-split)
        {
            const int j = tid & 127, rp = (tid >> 7) & 1, half = tid >> 8;
            u64 acc = 0ull;
            const ulonglong2* hp = (const ulonglong2*)hicp[rp];
            const int k0 = half * 32;
            #pragma unroll 8
            for (int kg = k0; kg < k0 + 32; ++kg)
                gemm_kg(acc, gT4_Wh[kg * 128 + j], hp, kg);
            scrA[half * 256 + rp * 128 + j] = unp2(acc);
        }
        __syncthreads();
        if (tid < 256) {
            const int j = tid & 127, rp = tid >> 7;
            const float2 a = scrA[rp * 128 + j], b = scrA[256 + rp * 128 + j];
            qsp[rp][j] = make_float2(a.x + b.x, a.y + b.y);
        }
        __syncthreads();

        // scores
        for (int s = wno; s < 4 * TE; s += 16) {
            const int r = s / TE, tt = s % TE;
            const int rp = r >> 1, rh = r & 1;
            const float4 x = ((const float4*)(g_wx + ((r0 + r) * TE + tt) * NH))[lane];
            const float2 q0 = qsp[rp][4 * lane],     q1 = qsp[rp][4 * lane + 1];
            const float2 q2 = qsp[rp][4 * lane + 2], q3 = qsp[rp][4 * lane + 3];
            float acc;
            acc =      ftanh((rh ? q0.y : q0.x) + x.x) * vw4.x;
            acc = fmaf(ftanh((rh ? q1.y : q1.x) + x.y), vw4.y, acc);
            acc = fmaf(ftanh((rh ? q2.y : q2.x) + x.z), vw4.z, acc);
            acc = fmaf(ftanh((rh ? q3.y : q3.x) + x.w), vw4.w, acc);
            #pragma unroll
            for (int o = 16; o; o >>= 1) acc += __shfl_xor_sync(~0u, acc, o);
            if (lane == 0) ((float*)&ssp2[rp][tt])[rh] = acc + vb;
        }
        __syncthreads();

        // din partials (t-split)
        {
            const int j = tid & 127, rp = (tid >> 7) & 1, half = tid >> 8;
            u64 acc = 0ull;
            const u64* sp = (const u64*)ssp2[rp];
            const float2* mp = g_midp + ((p0 + rp) * TE) * NH + j;
            const int t0 = half * 84;
            #pragma unroll 4
            for (int tt = t0; tt < t0 + 84; ++tt) {
                const u64 m2 = *(const u64*)(mp + tt * NH);
                ffma2(acc, sp[tt], m2);
            }
            scrA[half * 256 + rp * 128 + j] = unp2(acc);
        }
        __syncthreads();
        if (tid < 256) {
            const int j = tid & 127, rp = tid >> 7;
            const float2 a = scrA[rp * 128 + j], b = scrA[256 + rp * 128 + j];
            dind[2 * rp][j]     = dup2(a.x + b.x);
            dind[2 * rp + 1][j] = dup2(a.y + b.y);
        }
        __syncthreads();

        // dec gates (col-pair lanes: half0 = Wih on din, half1 = Whh on hic)
        {
            const int cp = tid & 255, half = tid >> 8;
            u64 A0, A1, A2, A3;
            if (!half) {
                const float2 bi = ((const float2*)dbih)[cp];
                const float2 bh = ((const float2*)dbhh)[cp];
                A0 = pkf2(bi.x + bh.x, bi.y + bh.y);
            } else A0 = 0ull;
            A1 = A0; A2 = A0; A3 = A0;
            if (!half) {
                const ulonglong2* d0 = (const ulonglong2*)dind[0];
                const ulonglong2* d1 = (const ulonglong2*)dind[1];
                const ulonglong2* d2 = (const ulonglong2*)dind[2];
                const ulonglong2* d3 = (const ulonglong2*)dind[3];
                #pragma unroll 8
                for (int kb = 0; kb < 64; ++kb) {
                    const ulonglong2 wv = gP_dWih[kb * 256 + cp];
                    GKB(A0, wv, d0, kb); GKB(A1, wv, d1, kb);
                    GKB(A2, wv, d2, kb); GKB(A3, wv, d3, kb);
                }
            } else {
                const ulonglong2* h0 = (const ulonglong2*)hicd[0];
                const ulonglong2* h1 = (const ulonglong2*)hicd[1];
                const ulonglong2* h2 = (const ulonglong2*)hicd[2];
                const ulonglong2* h3 = (const ulonglong2*)hicd[3];
                #pragma unroll 8
                for (int kb = 0; kb < 64; ++kb) {
                    const ulonglong2 wv = gP_dWhh[kb * 256 + cp];
                    GKB(A0, wv, h0, kb); GKB(A1, wv, h1, kb);
                    GKB(A2, wv, h2, kb); GKB(A3, wv, h3, kb);
                }
            }
            scrG[half][cp][0] = A0; scrG[half][cp][1] = A1;
            scrG[half][cp][2] = A2; scrG[half][cp][3] = A3;
        }
        __syncthreads();

        // dec LSTM update
        {
            const int j = tid & 127, r = tid >> 7;
            const int jc = j >> 1, jl = j & 1;
            const float gi = ((const float*)&scrG[0][jc      ][r])[jl] + ((const float*)&scrG[1][jc      ][r])[jl];
            const float gf = ((const float*)&scrG[0][jc +  64][r])[jl] + ((const float*)&scrG[1][jc +  64][r])[jl];
            const float gg = ((const float*)&scrG[0][jc + 128][r])[jl] + ((const float*)&scrG[1][jc + 128][r])[jl];
            const float go = ((const float*)&scrG[0][jc + 192][r])[jl] + ((const float*)&scrG[1][jc + 192][r])[jl];
            const float co = ((const float*)&hicp[r >> 1][128 + j])[r & 1];
            const float cn = fsigm(gf) * co + fsigm(gi) * ftanh(gg);
            const float hn = fsigm(go) * ftanh(cn);
            ((float*)&hicp[r >> 1][j])[r & 1]       = hn;
            ((float*)&hicp[r >> 1][128 + j])[r & 1] = cn;
            hicd[r][j] = dup2(hn);
        }
        __syncthreads();

        // out head
        if (wno < 4) {
            const int rp = wno >> 1, rh = wno & 1;
            const float2 h0 = hicp[rp][lane],      h1 = hicp[rp][lane + 32];
            const float2 h2 = hicp[rp][lane + 64], h3 = hicp[rp][lane + 96];
            float acc =       (rh ? h0.y : h0.x) * regw[lane];
            acc = fmaf((rh ? h1.y : h1.x), regw[lane + 32], acc);
            acc = fmaf((rh ? h2.y : h2.x), regw[lane + 64], acc);
            acc = fmaf((rh ? h3.y : h3.x), regw[lane + 96], acc);
            #pragma unroll
            for (int o = 16; o; o >>= 1) acc += __shfl_xor_sync(~0u, acc, o);
            if (lane == 0) out[(r0 + wno) * TD + td] = acc + regb[0];
        }
        __syncthreads();
    }
}

extern "C" void kernel_launch(void* const* d_in, const int* in_sizes, int n_in,
                              void* d_out, int out_size)
{
    const float* X    = (const float*)d_in[0];
    const float* Wi_w = (const float*)d_in[2];
    const float* Wi_b = (const float*)d_in[3];
    const float* We_w = (const float*)d_in[4];
    const float* Vd_w = (const float*)d_in[5];
    const float* Vd_b = (const float*)d_in[6];
    const float* eWih = (const float*)d_in[7];
    const float* eWhh = (const float*)d_in[8];
    const float* ebih = (const float*)d_in[9];
    const float* ebhh = (const float*)d_in[10];
    const float* mWih = (const float*)d_in[11];
    const float* mWhh = (const float*)d_in[12];
    const float* mbih = (const float*)d_in[13];
    const float* mbhh = (const float*)d_in[14];
    const float* Wx_w = (const float*)d_in[15];
    const float* Wx_b = (const float*)d_in[16];
    const float* Wh_w = (const float*)d_in[17];
    const float* V_w  = (const float*)d_in[18];
    const float* V_b  = (const float*)d_in[19];
    const float* dWih = (const float*)d_in[20];
    const float* dWhh = (const float*)d_in[21];
    const float* dbih = (const float*)d_in[22];
    const float* dbhh = (const float*)d_in[23];
    const float* regw = (const float*)d_in[24];
    const float* regb = (const float*)d_in[25];

    k_tr<<<256, 256>>>(eWih, eWhh, mWih, mWhh, dWih, dWhh,
                       We_w, Wi_w, Vd_w, Wh_w, Wx_w);
    k_enc_mid<<<NB / 4, 512>>>(X, Wi_b, Vd_b, ebih, ebhh, mbih, mbhh);
    k_wx<<<(NB / 2 * TE) / 16, 256>>>(Wx_b);
    k_dec<<<NB / 4, 512>>>(V_w, V_b, dbih, dbhh, regw, regb, (float*)d_out);
}

// round 14
// speedup vs baseline: 1.0991x; 1.0991x over previous
#include <cuda_runtime.h>
#include <math.h>

#define NB 1024
#define TE 168
#define TD 24
#define NF 64
#define NH 128

typedef unsigned long long u64;

// ---- globals ----
__device__ float2 g_hencp[(NB/2) * TE * NH];   // enc h, paired
__device__ float2 g_midp [(NB/2) * TE * NH];   // mid h, paired
__device__ float2 g_P    [(NB/2) * TE * 512];  // mid input-projection, paired
__device__ float  g_wx   [NB * TE * NH];
__device__ float2 g_hmp  [(NB/2) * NH];
__device__ float2 g_cmp  [(NB/2) * NH];

// fp32 float4-packed k-major weights: gT4[kg*C + c] = {W[c][4kg..4kg+3]}
__device__ float4 gT4_eWih[16 * 512];
__device__ float4 gT4_eWhh[32 * 512];
__device__ float4 gT4_mWih[32 * 512];
__device__ float4 gT4_mWhh[32 * 512];
__device__ float4 gT4_dWih[32 * 512];
__device__ float4 gT4_dWhh[32 * 512];
__device__ float4 gT4_We [64 * 128];
__device__ float4 gT4_Wi [16 * 128];
__device__ float4 gT4_Vd [32 * 64];
__device__ float4 gT4_Wh [64 * 128];
__device__ float4 gT4_Wx [32 * 128];

__device__ __forceinline__ float ftanh(float x) {
    x = fminf(15.0f, fmaxf(-15.0f, x));
    const float e = __expf(2.0f * x);
    return __fdividef(e - 1.0f, e + 1.0f);
}
__device__ __forceinline__ float fsigm(float x) {
    return __fdividef(1.0f, 1.0f + __expf(-x));
}
__device__ __forceinline__ u64 dup2(float x) {
    u64 r; asm("mov.b64 %0, {%1, %1};" : "=l"(r) : "f"(x)); return r;
}
__device__ __forceinline__ float2 unp2(u64 v) {
    float2 r; asm("mov.b64 {%0, %1}, %2;" : "=f"(r.x), "=f"(r.y) : "l"(v)); return r;
}
__device__ __forceinline__ void ffma2(u64& d, u64 a, u64 b) {
    asm("fma.rn.f32x2 %0, %1, %2, %0;" : "+l"(d) : "l"(a), "l"(b));
}
__device__ __forceinline__ void gemm_kg(u64& acc, const float4 w,
                                        const ulonglong2* __restrict__ act, int kg)
{
    const u64 w0 = dup2(w.x), w1 = dup2(w.y), w2 = dup2(w.z), w3 = dup2(w.w);
    const ulonglong2 a01 = act[2 * kg];
    const ulonglong2 a23 = act[2 * kg + 1];
    ffma2(acc, w0, a01.x); ffma2(acc, w1, a01.y);
    ffma2(acc, w2, a23.x); ffma2(acc, w3, a23.y);
}

// ---------------- Kernel 0: pack weights ----------------
__device__ __forceinline__ void packW4(const float* __restrict__ W, float4* dst,
                                       int C, int K, int i0, int st)
{
    const int n = C * (K >> 2);
    for (int i = i0; i < n; i += st) {
        const int c = i % C, kg = i / C;
        const float* p = W + c * K + kg * 4;
        dst[i] = make_float4(p[0], p[1], p[2], p[3]);
    }
}

__global__ void k_tr(const float* __restrict__ eWih, const float* __restrict__ eWhh,
                     const float* __restrict__ mWih, const float* __restrict__ mWhh,
                     const float* __restrict__ dWih, const float* __restrict__ dWhh,
                     const float* __restrict__ We,   const float* __restrict__ Wi,
                     const float* __restrict__ Vd,   const float* __restrict__ Wh,
                     const float* __restrict__ Wx)
{
    const int i0 = blockIdx.x * blockDim.x + threadIdx.x;
    const int st = gridDim.x * blockDim.x;
    packW4(eWih, gT4_eWih, 512, 64,  i0, st);
    packW4(eWhh, gT4_eWhh, 512, 128, i0, st);
    packW4(mWih, gT4_mWih, 512, 128, i0, st);
    packW4(mWhh, gT4_mWhh, 512, 128, i0, st);
    packW4(dWih, gT4_dWih, 512, 128, i0, st);
    packW4(dWhh, gT4_dWhh, 512, 128, i0, st);
    packW4(We,   gT4_We,   128, 256, i0, st);
    packW4(Wi,   gT4_Wi,   128, 64,  i0, st);
    packW4(Vd,   gT4_Vd,   64,  128, i0, st);
    packW4(Wh,   gT4_Wh,   128, 256, i0, st);
    packW4(Wx,   gT4_Wx,   128, 128, i0, st);
}

// ---------------- Kernel 1: encoder recurrence (smem-cached eWih/Wi/Vd) ----------------
// dynamic smem: [0..2048) Wi, [2048..4096) Vd, [4096..12288) eWih  (float4, 192KB)
__global__ __launch_bounds__(1024, 1)
void k_enc(const float* __restrict__ X,
           const float* __restrict__ Wi_b, const float* __restrict__ Vd_b,
           const float* __restrict__ ebih, const float* __restrict__ ebhh)
{
    extern __shared__ float4 dsm[];
    float4* sWi   = dsm;
    float4* sVd   = dsm + 2048;
    float4* seWih = dsm + 4096;

    __shared__ __align__(16) float2 hcp [4][256];
    __shared__ __align__(16) float2 xtp [4][64];
    __shared__ __align__(16) float2 xinp[4][64];
    __shared__ __align__(16) float2 t1p [4][128];
    __shared__ __align__(16) float2 scr [2048];

    const int tid = threadIdx.x;
    const int r0  = blockIdx.x * 8;
    const int p0  = blockIdx.x * 4;
    const int wno = tid >> 5, lane = tid & 31;

    for (int i = tid; i < 2048; i += 1024) { sWi[i] = gT4_Wi[i]; sVd[i] = gT4_Vd[i]; }
    for (int i = tid; i < 8192; i += 1024) seWih[i] = gT4_eWih[i];
    {
        const int rp = tid >> 8, k = tid & 255;
        hcp[rp][k] = make_float2(0.f, 0.f);
    }
    __syncthreads();

    for (int t = 0; t < TE; ++t) {
        if (tid < 512) {
            const int f = tid & 63, rp = (tid >> 6) & 3, half = tid >> 8;
            ((float*)&xtp[rp][f])[half] = X[((r0 + 2 * rp + half) * TE + t) * NF + f];
        }
        __syncthreads();

        // t1 partials: (j, rp, half) k-split 40 / 24+Wi16
        {
            const int j = tid & 127, rp = (tid >> 7) & 3, half = tid >> 9;
            const ulonglong2* hp = (const ulonglong2*)hcp[rp];
            u64 acc;
            if (!half) {
                acc = dup2(Wi_b[j]);
                #pragma unroll 8
                for (int kg = 0; kg < 40; ++kg)
                    gemm_kg(acc, gT4_We[kg * 128 + j], hp, kg);
            } else {
                acc = 0ull;
                #pragma unroll 8
                for (int kg = 40; kg < 64; ++kg)
                    gemm_kg(acc, gT4_We[kg * 128 + j], hp, kg);
                const ulonglong2* xp = (const ulonglong2*)xtp[rp];
                #pragma unroll
                for (int kg = 0; kg < 16; ++kg)
                    gemm_kg(acc, sWi[kg * 128 + j], xp, kg);
            }
            scr[half * 512 + rp * 128 + j] = unp2(acc);
        }
        __syncthreads();

        if (tid < 512) {
            const int j = tid & 127, rp = tid >> 7;
            const float2 a = scr[rp * 128 + j], b = scr[512 + rp * 128 + j];
            t1p[rp][j] = make_float2(ftanh(a.x + b.x), ftanh(a.y + b.y));
        }
        __syncthreads();

        // s partials (Vd cached)
        if (tid < 512) {
            const int f = tid & 63, rp = (tid >> 6) & 3, half = tid >> 8;
            u64 acc = half ? 0ull : dup2(Vd_b[f]);
            const ulonglong2* tp = (const ulonglong2*)t1p[rp];
            const int k0 = half * 16;
            #pragma unroll 8
            for (int kg = k0; kg < k0 + 16; ++kg)
                gemm_kg(acc, sVd[kg * 64 + f], tp, kg);
            scr[1024 + half * 256 + rp * 64 + f] = unp2(acc);
        }
        __syncthreads();

        // softmax + x_in : warps 0..7
        if (wno < 8) {
            const int rp = wno >> 1, rh = wno & 1;
            const float2 a0 = scr[1024 + rp * 64 + lane];
            const float2 b0 = scr[1280 + rp * 64 + lane];
            const float2 a1 = scr[1024 + rp * 64 + lane + 32];
            const float2 b1 = scr[1280 + rp * 64 + lane + 32];
            float v0 = rh ? (a0.y + b0.y) : (a0.x + b0.x);
            float v1 = rh ? (a1.y + b1.y) : (a1.x + b1.x);
            float mx = fmaxf(v0, v1);
            #pragma unroll
            for (int o = 16; o; o >>= 1) mx = fmaxf(mx, __shfl_xor_sync(~0u, mx, o));
            float e0 = __expf(v0 - mx), e1 = __expf(v1 - mx);
            float sm = e0 + e1;
            #pragma unroll
            for (int o = 16; o; o >>= 1) sm += __shfl_xor_sync(~0u, sm, o);
            const float inv = __fdividef(1.0f, sm);
            const float2 x0 = xtp[rp][lane], x1 = xtp[rp][lane + 32];
            ((float*)&xinp[rp][lane])[rh]      = (rh ? x0.y : x0.x) * e0 * inv;
            ((float*)&xinp[rp][lane + 32])[rh] = (rh ? x1.y : x1.x) * e1 * inv;
        }
        __syncthreads();

        // enc gates: thread = (c, rpg); eWih from smem, eWhh streamed
        {
            const int c = tid & 511, rpg = tid >> 9;
            const int ra = rpg * 2, rb = rpg * 2 + 1;
            const u64 bini = dup2(ebih[c] + ebhh[c]);
            u64 A0 = bini, A1 = bini;
            #pragma unroll 4
            for (int kg = 0; kg < 16; ++kg) {
                const float4 w = seWih[kg * 512 + c];
                gemm_kg(A0, w, (const ulonglong2*)xinp[ra], kg);
                gemm_kg(A1, w, (const ulonglong2*)xinp[rb], kg);
            }
            #pragma unroll 4
            for (int kg = 0; kg < 32; ++kg) {
                const float4 w = gT4_eWhh[kg * 512 + c];
                gemm_kg(A0, w, (const ulonglong2*)hcp[ra], kg);
                gemm_kg(A1, w, (const ulonglong2*)hcp[rb], kg);
            }
            scr[ra * 512 + c] = unp2(A0);
            scr[rb * 512 + c] = unp2(A1);
        }
        __syncthreads();

        // enc LSTM update + g_hencp store
        {
            const int j = tid & 127, rp = (tid >> 7) & 3, half = tid >> 9;
            const float gi = ((const float*)&scr[rp * 512 + j      ])[half];
            const float gf = ((const float*)&scr[rp * 512 + j + 128])[half];
            const float gg = ((const float*)&scr[rp * 512 + j + 256])[half];
            const float go = ((const float*)&scr[rp * 512 + j + 384])[half];
            const float co = ((const float*)&hcp[rp][128 + j])[half];
            const float cn = fsigm(gf) * co + fsigm(gi) * ftanh(gg);
            const float hn = fsigm(go) * ftanh(cn);
            ((float*)&hcp[rp][j])[half]       = hn;
            ((float*)&hcp[rp][128 + j])[half] = cn;
            ((float*)&g_hencp[((p0 + rp) * TE + t) * NH + j])[half] = hn;
        }
        __syncthreads();
    }
}

// ---------------- Kernel 2: mid input projection P = h_enc @ mWih^T + b ----------------
__global__ __launch_bounds__(512, 1)
void k_midproj(const float* __restrict__ mbih, const float* __restrict__ mbhh)
{
    __shared__ __align__(16) float2 msp[8][128];
    const int tid = threadIdx.x;
    const int ub  = blockIdx.x * 8;

    for (int i = tid; i < 8 * 128; i += 512)
        msp[i >> 7][i & 127] = g_hencp[ub * NH + i];
    __syncthreads();

    const int c = tid;
    const u64 bini = dup2(mbih[c] + mbhh[c]);
    u64 acc[8];
    #pragma unroll
    for (int u = 0; u < 8; ++u) acc[u] = bini;

    #pragma unroll 4
    for (int kg = 0; kg < 32; ++kg) {
        const float4 w = gT4_mWih[kg * 512 + c];
        #pragma unroll
        for (int u = 0; u < 8; ++u)
            gemm_kg(acc[u], w, (const ulonglong2*)msp[u], kg);
    }
    #pragma unroll
    for (int u = 0; u < 8; ++u)
        *(u64*)&g_P[(u64)(ub + u) * 512 + c] = acc[u];
}

// ---------------- Kernel 3: mid recurrence (mWhh smem-cached 200KB) ----------------
// dynamic smem: wsm[12800] float4 = mWhh kg 0..24 (200KB); kg 25..31 streamed
__global__ __launch_bounds__(1024, 1)
void k_mid()
{
    extern __shared__ float4 wsm[];
    __shared__ __align__(16) float2 hmp[4][128];
    __shared__ __align__(16) float2 cmp[4][128];
    __shared__ __align__(16) float2 scr[2048];

    const int tid = threadIdx.x;
    const int p0  = blockIdx.x * 4;

    for (int i = tid; i < 12800; i += 1024) wsm[i] = gT4_mWhh[i];
    if (tid < 512) {
        const int rp = tid >> 7, j = tid & 127;
        hmp[rp][j] = make_float2(0.f, 0.f);
        cmp[rp][j] = make_float2(0.f, 0.f);
    }
    __syncthreads();

    for (int t = 0; t < TE; ++t) {
        // gates: thread = (c, rpg); init from precomputed P
        {
            const int c = tid & 511, rpg = tid >> 9;
            const int ra = rpg * 2, rb = rpg * 2 + 1;
            u64 A0 = *(const u64*)&g_P[(u64)((p0 + ra) * TE + t) * 512 + c];
            u64 A1 = *(const u64*)&g_P[(u64)((p0 + rb) * TE + t) * 512 + c];
            #pragma unroll 5
            for (int kg = 0; kg < 25; ++kg) {
                const float4 w = wsm[kg * 512 + c];
                gemm_kg(A0, w, (const ulonglong2*)hmp[ra], kg);
                gemm_kg(A1, w, (const ulonglong2*)hmp[rb], kg);
            }
            #pragma unroll
            for (int kg = 25; kg < 32; ++kg) {
                const float4 w = gT4_mWhh[kg * 512 + c];
                gemm_kg(A0, w, (const ulonglong2*)hmp[ra], kg);
                gemm_kg(A1, w, (const ulonglong2*)hmp[rb], kg);
            }
            scr[ra * 512 + c] = unp2(A0);
            scr[rb * 512 + c] = unp2(A1);
        }
        __syncthreads();

        // mid LSTM update + g_midp store
        {
            const int j = tid & 127, rp = (tid >> 7) & 3, half = tid >> 9;
            const float gi = ((const float*)&scr[rp * 512 + j      ])[half];
            const float gf = ((const float*)&scr[rp * 512 + j + 128])[half];
            const float gg = ((const float*)&scr[rp * 512 + j + 256])[half];
            const float go = ((const float*)&scr[rp * 512 + j + 384])[half];
            const float co = ((const float*)&cmp[rp][j])[half];
            const float cn = fsigm(gf) * co + fsigm(gi) * ftanh(gg);
            const float hn = fsigm(go) * ftanh(cn);
            ((float*)&hmp[rp][j])[half] = hn;
            ((float*)&cmp[rp][j])[half] = cn;
            ((float*)&g_midp[((p0 + rp) * TE + t) * NH + j])[half] = hn;
        }
        __syncthreads();
    }

    if (tid < 512) {
        const int rp = tid >> 7, j = tid & 127;
        g_hmp[(p0 + rp) * NH + j] = hmp[rp][j];
        g_cmp[(p0 + rp) * NH + j] = cmp[rp][j];
    }
}

// ---------------- Kernel 4: wx_mid ----------------
__global__ __launch_bounds__(256, 1)
void k_wx(const float* __restrict__ Wx_b)
{
    __shared__ __align__(16) float2 msp[16][128];
    const int tid = threadIdx.x;
    const int ub  = blockIdx.x * 16;

    for (int i = tid; i < 16 * 128; i += 256)
        msp[i >> 7][i & 127] = g_midp[ub * NH + i];
    __syncthreads();

    const int j = tid & 127, rg = tid >> 7;
    const u64 bini = dup2(Wx_b[j]);
    u64 acc[8];
    #pragma unroll
    for (int u = 0; u < 8; ++u) acc[u] = bini;

    #pragma unroll 4
    for (int kg = 0; kg < 32; ++kg) {
        const float4 w = gT4_Wx[kg * 128 + j];
        #pragma unroll
        for (int u = 0; u < 8; ++u)
            gemm_kg(acc[u], w, (const ulonglong2*)msp[rg * 8 + u], kg);
    }
    #pragma unroll
    for (int u = 0; u < 8; ++u) {
        const int gu = ub + rg * 8 + u;
        const int pair = gu / TE, tt = gu % TE;
        const float2 r = unp2(acc[u]);
        g_wx[((2 * pair)     * TE + tt) * NH + j] = r.x;
        g_wx[((2 * pair + 1) * TE + tt) * NH + j] = r.y;
    }
}

// ---------------- Kernel 5: decoder (R11, unchanged) ----------------
__global__ __launch_bounds__(512, 2)
void k_dec(const float* __restrict__ V_w,  const float* __restrict__ V_b,
           const float* __restrict__ dbih, const float* __restrict__ dbhh,
           const float* __restrict__ regw, const float* __restrict__ regb,
           float* __restrict__ out)
{
    __shared__ __align__(16) float2 hicp[2][256];
    __shared__ __align__(16) float2 qsp [2][128];
    __shared__ __align__(16) float2 ssp2[2][TE];
    __shared__ __align__(16) float2 dinp[2][128];
    __shared__ __align__(16) float2 scr [1024];

    const int tid = threadIdx.x;
    const int r0  = blockIdx.x * 4;
    const int p0  = blockIdx.x * 2;
    const int wno = tid >> 5, lane = tid & 31;

    const float4 vw4 = ((const float4*)V_w)[lane];
    const float  vb  = V_b[0];

    {
        const int rp = tid >> 8, k = tid & 255;
        hicp[rp][k] = (k < 128) ? g_hmp[(p0 + rp) * NH + k]
                                : g_cmp[(p0 + rp) * NH + (k - 128)];
    }
    __syncthreads();

    for (int td = 0; td < TD; ++td) {
        {
            const int j = tid & 127, rp = (tid >> 7) & 1, half = tid >> 8;
            u64 acc = 0ull;
            const ulonglong2* hp = (const ulonglong2*)hicp[rp];
            const int k0 = half * 32;
            #pragma unroll 8
            for (int kg = k0; kg < k0 + 32; ++kg)
                gemm_kg(acc, gT4_Wh[kg * 128 + j], hp, kg);
            scr[half * 256 + rp * 128 + j] = unp2(acc);
        }
        __syncthreads();
        if (tid < 256) {
            const int j = tid & 127, rp = tid >> 7;
            const float2 a = scr[rp * 128 + j], b = scr[256 + rp * 128 + j];
            qsp[rp][j] = make_float2(a.x + b.x, a.y + b.y);
        }
        __syncthreads();

        for (int s = wno; s < 4 * TE; s += 16) {
            const int r = s / TE, tt = s % TE;
            const int rp = r >> 1, rh = r & 1;
            const float4 x = ((const float4*)(g_wx + ((r0 + r) * TE + tt) * NH))[lane];
            const float2 q0 = qsp[rp][4 * lane],     q1 = qsp[rp][4 * lane + 1];
            const float2 q2 = qsp[rp][4 * lane + 2], q3 = qsp[rp][4 * lane + 3];
            float acc;
            acc =      ftanh((rh ? q0.y : q0.x) + x.x) * vw4.x;
            acc = fmaf(ftanh((rh ? q1.y : q1.x) + x.y), vw4.y, acc);
            acc = fmaf(ftanh((rh ? q2.y : q2.x) + x.z), vw4.z, acc);
            acc = fmaf(ftanh((rh ? q3.y : q3.x) + x.w), vw4.w, acc);
            #pragma unroll
            for (int o = 16; o; o >>= 1) acc += __shfl_xor_sync(~0u, acc, o);
            if (lane == 0) ((float*)&ssp2[rp][tt])[rh] = acc + vb;
        }
        __syncthreads();

        {
            const int j = tid & 127, rp = (tid >> 7) & 1, half = tid >> 8;
            u64 acc = 0ull;
            const u64* sp = (const u64*)ssp2[rp];
            const float2* mp = g_midp + ((p0 + rp) * TE) * NH + j;
            const int t0 = half * 84;
            #pragma unroll 4
            for (int tt = t0; tt < t0 + 84; ++tt) {
                const u64 m2 = *(const u64*)(mp + tt * NH);
                ffma2(acc, sp[tt], m2);
            }
            scr[half * 256 + rp * 128 + j] = unp2(acc);
        }
        __syncthreads();
        if (tid < 256) {
            const int j = tid & 127, rp = tid >> 7;
            const float2 a = scr[rp * 128 + j], b = scr[256 + rp * 128 + j];
            dinp[rp][j] = make_float2(a.x + b.x, a.y + b.y);
        }
        __syncthreads();

        {
            const int c = tid;
            const u64 bini = dup2(dbih[c] + dbhh[c]);
            u64 A0 = bini, A1 = bini;
            #pragma unroll 4
            for (int kg = 0; kg < 32; ++kg) {
                const float4 w = gT4_dWih[kg * 512 + c];
                gemm_kg(A0, w, (const ulonglong2*)dinp[0], kg);
                gemm_kg(A1, w, (const ulonglong2*)dinp[1], kg);
            }
            #pragma unroll 4
            for (int kg = 0; kg < 32; ++kg) {
                const float4 w = gT4_dWhh[kg * 512 + c];
                gemm_kg(A0, w, (const ulonglong2*)hicp[0], kg);
                gemm_kg(A1, w, (const ulonglong2*)hicp[1], kg);
            }
            scr[c] = unp2(A0); scr[512 + c] = unp2(A1);
        }
        __syncthreads();

        {
            const int j = tid & 127, rp = (tid >> 7) & 1, half = tid >> 8;
            const float gi = ((const float*)&scr[rp * 512 + j      ])[half];
            const float gf = ((const float*)&scr[rp * 512 + j + 128])[half];
            const float gg = ((const float*)&scr[rp * 512 + j + 256])[half];
            const float go = ((const float*)&scr[rp * 512 + j + 384])[half];
            const float co = ((const float*)&hicp[rp][128 + j])[half];
            const float cn = fsigm(gf) * co + fsigm(gi) * ftanh(gg);
            const float hn = fsigm(go) * ftanh(cn);
            ((float*)&hicp[rp][j])[half]       = hn;
            ((float*)&hicp[rp][128 + j])[half] = cn;
        }
        __syncthreads();

        if (wno < 4) {
            const int rp = wno >> 1, rh = wno & 1;
            const float2 h0 = hicp[rp][lane],      h1 = hicp[rp][lane + 32];
            const float2 h2 = hicp[rp][lane + 64], h3 = hicp[rp][lane + 96];
            float acc =       (rh ? h0.y : h0.x) * regw[lane];
            acc = fmaf((rh ? h1.y : h1.x), regw[lane + 32], acc);
            acc = fmaf((rh ? h2.y : h2.x), regw[lane + 64], acc);
            acc = fmaf((rh ? h3.y : h3.x), regw[lane + 96], acc);
            #pragma unroll
            for (int o = 16; o; o >>= 1) acc += __shfl_xor_sync(~0u, acc, o);
            if (lane == 0) out[(r0 + wno) * TD + td] = acc + regb[0];
        }
        __syncthreads();
    }
}

extern "C" void kernel_launch(void* const* d_in, const int* in_sizes, int n_in,
                              void* d_out, int out_size)
{
    const float* X    = (const float*)d_in[0];
    const float* Wi_w = (const float*)d_in[2];
    const float* Wi_b = (const float*)d_in[3];
    const float* We_w = (const float*)d_in[4];
    const float* Vd_w = (const float*)d_in[5];
    const float* Vd_b = (const float*)d_in[6];
    const float* eWih = (const float*)d_in[7];
    const float* eWhh = (const float*)d_in[8];
    const float* ebih = (const float*)d_in[9];
    const float* ebhh = (const float*)d_in[10];
    const float* mWih = (const float*)d_in[11];
    const float* mWhh = (const float*)d_in[12];
    const float* mbih = (const float*)d_in[13];
    const float* mbhh = (const float*)d_in[14];
    const float* Wx_w = (const float*)d_in[15];
    const float* Wx_b = (const float*)d_in[16];
    const float* Wh_w = (const float*)d_in[17];
    const float* V_w  = (const float*)d_in[18];
    const float* V_b  = (const float*)d_in[19];
    const float* dWih = (const float*)d_in[20];
    const float* dWhh = (const float*)d_in[21];
    const float* dbih = (const float*)d_in[22];
    const float* dbhh = (const float*)d_in[23];
    const float* regw = (const float*)d_in[24];
    const float* regb = (const float*)d_in[25];

    cudaFuncSetAttribute(k_enc, cudaFuncAttributeMaxDynamicSharedMemorySize, 196608);
    cudaFuncSetAttribute(k_mid, cudaFuncAttributeMaxDynamicSharedMemorySize, 204800);

    k_tr<<<256, 256>>>(eWih, eWhh, mWih, mWhh, dWih, dWhh,
                       We_w, Wi_w, Vd_w, Wh_w, Wx_w);
    k_enc<<<NB / 8, 1024, 196608>>>(X, Wi_b, Vd_b, ebih, ebhh);
    k_midproj<<<(NB / 2 * TE) / 8, 512>>>(mbih, mbhh);
    k_mid<<<NB / 8, 1024, 204800>>>();
    k_wx<<<(NB / 2 * TE) / 16, 256>>>(Wx_b);
    k_dec<<<NB / 4, 512>>>(V_w, V_b, dbih, dbhh, regw, regb, (float*)d_out);
}

// round 15
// speedup vs baseline: 1.1355x; 1.0332x over previous
#include <cuda_runtime.h>
#include <math.h>

#define NB 1024
#define TE 168
#define TD 24
#define NF 64
#define NH 128

typedef unsigned long long u64;

// ---- globals ----
__device__ float2 g_hencp[(NB/2) * TE * NH];
__device__ float2 g_midp [(NB/2) * TE * NH];
__device__ float2 g_P    [(NB/2) * TE * 512];
__device__ float  g_wx   [NB * TE * NH];
__device__ float2 g_hmp  [(NB/2) * NH];
__device__ float2 g_cmp  [(NB/2) * NH];

// fp32 float4-packed k-major weights
__device__ float4 gT4_eWih[16 * 512];
__device__ float4 gT4_eWhh[32 * 512];
__device__ float4 gT4_mWih[32 * 512];
__device__ float4 gT4_mWhh[32 * 512];
__device__ float4 gT4_dWih[32 * 512];
__device__ float4 gT4_dWhh[32 * 512];
__device__ float4 gT4_We [64 * 128];
__device__ float4 gT4_Wi [16 * 128];
__device__ float4 gT4_Vd [32 * 64];
__device__ float4 gT4_Wh [64 * 128];
__device__ float4 gT4_Wx [32 * 128];

__device__ __forceinline__ float ftanh(float x) {
    x = fminf(15.0f, fmaxf(-15.0f, x));
    const float e = __expf(2.0f * x);
    return __fdividef(e - 1.0f, e + 1.0f);
}
__device__ __forceinline__ float fsigm(float x) {
    return __fdividef(1.0f, 1.0f + __expf(-x));
}
__device__ __forceinline__ u64 dup2(float x) {
    u64 r; asm("mov.b64 %0, {%1, %1};" : "=l"(r) : "f"(x)); return r;
}
__device__ __forceinline__ float2 unp2(u64 v) {
    float2 r; asm("mov.b64 {%0, %1}, %2;" : "=f"(r.x), "=f"(r.y) : "l"(v)); return r;
}
__device__ __forceinline__ void ffma2(u64& d, u64 a, u64 b) {
    asm("fma.rn.f32x2 %0, %1, %2, %0;" : "+l"(d) : "l"(a), "l"(b));
}
__device__ __forceinline__ void gemm_kg(u64& acc, const float4 w,
                                        const ulonglong2* __restrict__ act, int kg)
{
    const u64 w0 = dup2(w.x), w1 = dup2(w.y), w2 = dup2(w.z), w3 = dup2(w.w);
    const ulonglong2 a01 = act[2 * kg];
    const ulonglong2 a23 = act[2 * kg + 1];
    ffma2(acc, w0, a01.x); ffma2(acc, w1, a01.y);
    ffma2(acc, w2, a23.x); ffma2(acc, w3, a23.y);
}

// ---------------- Kernel 0: pack weights ----------------
__device__ __forceinline__ void packW4(const float* __restrict__ W, float4* dst,
                                       int C, int K, int i0, int st)
{
    const int n = C * (K >> 2);
    for (int i = i0; i < n; i += st) {
        const int c = i % C, kg = i / C;
        const float* p = W + c * K + kg * 4;
        dst[i] = make_float4(p[0], p[1], p[2], p[3]);
    }
}

__global__ void k_tr(const float* __restrict__ eWih, const float* __restrict__ eWhh,
                     const float* __restrict__ mWih, const float* __restrict__ mWhh,
                     const float* __restrict__ dWih, const float* __restrict__ dWhh,
                     const float* __restrict__ We,   const float* __restrict__ Wi,
                     const float* __restrict__ Vd,   const float* __restrict__ Wh,
                     const float* __restrict__ Wx)
{
    const int i0 = blockIdx.x * blockDim.x + threadIdx.x;
    const int st = gridDim.x * blockDim.x;
    packW4(eWih, gT4_eWih, 512, 64,  i0, st);
    packW4(eWhh, gT4_eWhh, 512, 128, i0, st);
    packW4(mWih, gT4_mWih, 512, 128, i0, st);
    packW4(mWhh, gT4_mWhh, 512, 128, i0, st);
    packW4(dWih, gT4_dWih, 512, 128, i0, st);
    packW4(dWhh, gT4_dWhh, 512, 128, i0, st);
    packW4(We,   gT4_We,   128, 256, i0, st);
    packW4(Wi,   gT4_Wi,   128, 64,  i0, st);
    packW4(Vd,   gT4_Vd,   64,  128, i0, st);
    packW4(Wh,   gT4_Wh,   128, 256, i0, st);
    packW4(Wx,   gT4_Wx,   128, 128, i0, st);
}

// ---------------- Kernel 1: encoder recurrence ----------------
// dynamic smem: [0..2048) Wi, [2048..10240) eWih  (float4, 160KB)
__global__ __launch_bounds__(1024, 1)
void k_enc(const float* __restrict__ X,
           const float* __restrict__ Wi_b, const float* __restrict__ Vd_b,
           const float* __restrict__ ebih, const float* __restrict__ ebhh)
{
    extern __shared__ float4 dsm[];
    float4* sWi   = dsm;
    float4* seWih = dsm + 2048;

    __shared__ __align__(16) float2 hcp [4][256];
    __shared__ __align__(16) float2 xtp [4][64];
    __shared__ __align__(16) float2 xinp[4][64];
    __shared__ __align__(16) float2 t1p [4][128];
    __shared__ __align__(16) u64    scrU[2][4][512];   // 32KB; [s][rp][c]

    float2* scrF = (float2*)scrU;   // alias for t1/s partials (disjoint in time)

    const int tid = threadIdx.x;
    const int r0  = blockIdx.x * 8;
    const int p0  = blockIdx.x * 4;
    const int wno = tid >> 5, lane = tid & 31;

    for (int i = tid; i < 2048; i += 1024) sWi[i] = gT4_Wi[i];
    for (int i = tid; i < 8192; i += 1024) seWih[i] = gT4_eWih[i];
    {
        const int rp = tid >> 8, k = tid & 255;
        hcp[rp][k] = make_float2(0.f, 0.f);
    }
    __syncthreads();

    for (int t = 0; t < TE; ++t) {
        if (tid < 512) {
            const int f = tid & 63, rp = (tid >> 6) & 3, half = tid >> 8;
            ((float*)&xtp[rp][f])[half] = X[((r0 + 2 * rp + half) * TE + t) * NF + f];
        }
        __syncthreads();

        // t1 partials
        {
            const int j = tid & 127, rp = (tid >> 7) & 3, half = tid >> 9;
            const ulonglong2* hp = (const ulonglong2*)hcp[rp];
            u64 acc;
            if (!half) {
                acc = dup2(Wi_b[j]);
                #pragma unroll 8
                for (int kg = 0; kg < 40; ++kg)
                    gemm_kg(acc, gT4_We[kg * 128 + j], hp, kg);
            } else {
                acc = 0ull;
                #pragma unroll 8
                for (int kg = 40; kg < 64; ++kg)
                    gemm_kg(acc, gT4_We[kg * 128 + j], hp, kg);
                const ulonglong2* xp = (const ulonglong2*)xtp[rp];
                #pragma unroll
                for (int kg = 0; kg < 16; ++kg)
                    gemm_kg(acc, sWi[kg * 128 + j], xp, kg);
            }
            scrF[half * 512 + rp * 128 + j] = unp2(acc);
        }
        __syncthreads();

        if (tid < 512) {
            const int j = tid & 127, rp = tid >> 7;
            const float2 a = scrF[rp * 128 + j], b = scrF[512 + rp * 128 + j];
            t1p[rp][j] = make_float2(ftanh(a.x + b.x), ftanh(a.y + b.y));
        }
        __syncthreads();

        // s partials (Vd streamed)
        if (tid < 512) {
            const int f = tid & 63, rp = (tid >> 6) & 3, half = tid >> 8;
            u64 acc = half ? 0ull : dup2(Vd_b[f]);
            const ulonglong2* tp = (const ulonglong2*)t1p[rp];
            const int k0 = half * 16;
            #pragma unroll 8
            for (int kg = k0; kg < k0 + 16; ++kg)
                gemm_kg(acc, gT4_Vd[kg * 64 + f], tp, kg);
            scrF[1024 + half * 256 + rp * 64 + f] = unp2(acc);
        }
        __syncthreads();

        // softmax + x_in
        if (wno < 8) {
            const int rp = wno >> 1, rh = wno & 1;
            const float2 a0 = scrF[1024 + rp * 64 + lane];
            const float2 b0 = scrF[1280 + rp * 64 + lane];
            const float2 a1 = scrF[1024 + rp * 64 + lane + 32];
            const float2 b1 = scrF[1280 + rp * 64 + lane + 32];
            float v0 = rh ? (a0.y + b0.y) : (a0.x + b0.x);
            float v1 = rh ? (a1.y + b1.y) : (a1.x + b1.x);
            float mx = fmaxf(v0, v1);
            #pragma unroll
            for (int o = 16; o; o >>= 1) mx = fmaxf(mx, __shfl_xor_sync(~0u, mx, o));
            float e0 = __expf(v0 - mx), e1 = __expf(v1 - mx);
            float sm = e0 + e1;
            #pragma unroll
            for (int o = 16; o; o >>= 1) sm += __shfl_xor_sync(~0u, sm, o);
            const float inv = __fdividef(1.0f, sm);
            const float2 x0 = xtp[rp][lane], x1 = xtp[rp][lane + 32];
            ((float*)&xinp[rp][lane])[rh]      = (rh ? x0.y : x0.x) * e0 * inv;
            ((float*)&xinp[rp][lane + 32])[rh] = (rh ? x1.y : x1.x) * e1 * inv;
        }
        __syncthreads();

        // enc gates: thread = (c, s); each covers ALL 4 row-pairs (weights loaded once)
        {
            const int c = tid & 511, s = tid >> 9;
            u64 A0, A1, A2, A3;
            if (!s) {
                const u64 bini = dup2(ebih[c] + ebhh[c]);
                A0 = bini; A1 = bini; A2 = bini; A3 = bini;
                #pragma unroll 4
                for (int kg = 0; kg < 16; ++kg) {
                    const float4 w = seWih[kg * 512 + c];
                    gemm_kg(A0, w, (const ulonglong2*)xinp[0], kg);
                    gemm_kg(A1, w, (const ulonglong2*)xinp[1], kg);
                    gemm_kg(A2, w, (const ulonglong2*)xinp[2], kg);
                    gemm_kg(A3, w, (const ulonglong2*)xinp[3], kg);
                }
                #pragma unroll 4
                for (int kg = 0; kg < 8; ++kg) {
                    const float4 w = gT4_eWhh[kg * 512 + c];
                    gemm_kg(A0, w, (const ulonglong2*)hcp[0], kg);
                    gemm_kg(A1, w, (const ulonglong2*)hcp[1], kg);
                    gemm_kg(A2, w, (const ulonglong2*)hcp[2], kg);
                    gemm_kg(A3, w, (const ulonglong2*)hcp[3], kg);
                }
            } else {
                A0 = 0ull; A1 = 0ull; A2 = 0ull; A3 = 0ull;
                #pragma unroll 4
                for (int kg = 8; kg < 32; ++kg) {
                    const float4 w = gT4_eWhh[kg * 512 + c];
                    gemm_kg(A0, w, (const ulonglong2*)hcp[0], kg);
                    gemm_kg(A1, w, (const ulonglong2*)hcp[1], kg);
                    gemm_kg(A2, w, (const ulonglong2*)hcp[2], kg);
                    gemm_kg(A3, w, (const ulonglong2*)hcp[3], kg);
                }
            }
            scrU[s][0][c] = A0; scrU[s][1][c] = A1;
            scrU[s][2][c] = A2; scrU[s][3][c] = A3;
        }
        __syncthreads();

        // enc LSTM update + g_hencp store
        {
            const int j = tid & 127, rp = (tid >> 7) & 3, half = tid >> 9;
            const float gi = ((const float*)&scrU[0][rp][j      ])[half] + ((const float*)&scrU[1][rp][j      ])[half];
            const float gf = ((const float*)&scrU[0][rp][j + 128])[half] + ((const float*)&scrU[1][rp][j + 128])[half];
            const float gg = ((const float*)&scrU[0][rp][j + 256])[half] + ((const float*)&scrU[1][rp][j + 256])[half];
            const float go = ((const float*)&scrU[0][rp][j + 384])[half] + ((const float*)&scrU[1][rp][j + 384])[half];
            const float co = ((const float*)&hcp[rp][128 + j])[half];
            const float cn = fsigm(gf) * co + fsigm(gi) * ftanh(gg);
            const float hn = fsigm(go) * ftanh(cn);
            ((float*)&hcp[rp][j])[half]       = hn;
            ((float*)&hcp[rp][128 + j])[half] = cn;
            ((float*)&g_hencp[((p0 + rp) * TE + t) * NH + j])[half] = hn;
        }
        __syncthreads();
    }
}

// ---------------- Kernel 2: mid input projection ----------------
__global__ __launch_bounds__(512, 1)
void k_midproj(const float* __restrict__ mbih, const float* __restrict__ mbhh)
{
    __shared__ __align__(16) float2 msp[8][128];
    const int tid = threadIdx.x;
    const int ub  = blockIdx.x * 8;

    for (int i = tid; i < 8 * 128; i += 512)
        msp[i >> 7][i & 127] = g_hencp[ub * NH + i];
    __syncthreads();

    const int c = tid;
    const u64 bini = dup2(mbih[c] + mbhh[c]);
    u64 acc[8];
    #pragma unroll
    for (int u = 0; u < 8; ++u) acc[u] = bini;

    #pragma unroll 4
    for (int kg = 0; kg < 32; ++kg) {
        const float4 w = gT4_mWih[kg * 512 + c];
        #pragma unroll
        for (int u = 0; u < 8; ++u)
            gemm_kg(acc[u], w, (const ulonglong2*)msp[u], kg);
    }
    #pragma unroll
    for (int u = 0; u < 8; ++u)
        *(u64*)&g_P[(u64)(ub + u) * 512 + c] = acc[u];
}

// ---------------- Kernel 3: mid recurrence (weight-stationary: regs + smem) ----------------
// thread (c, s): kg [s*16, s*16+8) in REGISTERS, kg [s*16+8, s*16+16) from smem cache.
// dynamic smem wsm[16*512] float4 = 128KB: i<8 -> kg 8+i ; i>=8 -> kg 16+i
__global__ __launch_bounds__(1024, 1)
void k_mid()
{
    extern __shared__ float4 wsm[];
    __shared__ __align__(16) float2 hmp[4][128];
    __shared__ __align__(16) float2 cmp[4][128];
    __shared__ __align__(16) u64    scrU[2][4][512];

    const int tid = threadIdx.x;
    const int p0  = blockIdx.x * 4;
    const int c   = tid & 511, s = tid >> 9;

    for (int i = tid; i < 16 * 512; i += 1024) {
        const int ii = i >> 9, cc = i & 511;
        const int kg = (ii < 8) ? (8 + ii) : (16 + ii);
        wsm[i] = gT4_mWhh[kg * 512 + cc];
    }
    // register-resident weights: kg base = s*16, 8 kg
    float4 wr[8];
    {
        const int kb = s * 16;
        #pragma unroll
        for (int i = 0; i < 8; ++i) wr[i] = gT4_mWhh[(kb + i) * 512 + c];
    }
    if (tid < 512) {
        const int rp = tid >> 7, j = tid & 127;
        hmp[rp][j] = make_float2(0.f, 0.f);
        cmp[rp][j] = make_float2(0.f, 0.f);
    }
    __syncthreads();

    for (int t = 0; t < TE; ++t) {
        // gates: (c, s); P-init on s=0
        {
            u64 A0, A1, A2, A3;
            if (!s) {
                A0 = *(const u64*)&g_P[(u64)((p0 + 0) * TE + t) * 512 + c];
                A1 = *(const u64*)&g_P[(u64)((p0 + 1) * TE + t) * 512 + c];
                A2 = *(const u64*)&g_P[(u64)((p0 + 2) * TE + t) * 512 + c];
                A3 = *(const u64*)&g_P[(u64)((p0 + 3) * TE + t) * 512 + c];
            } else { A0 = 0ull; A1 = 0ull; A2 = 0ull; A3 = 0ull; }
            const int kb = s * 16;
            #pragma unroll
            for (int i = 0; i < 8; ++i) {
                const float4 w = wr[i];
                const int kg = kb + i;
                gemm_kg(A0, w, (const ulonglong2*)hmp[0], kg);
                gemm_kg(A1, w, (const ulonglong2*)hmp[1], kg);
                gemm_kg(A2, w, (const ulonglong2*)hmp[2], kg);
                gemm_kg(A3, w, (const ulonglong2*)hmp[3], kg);
            }
            #pragma unroll
            for (int i = 0; i < 8; ++i) {
                const float4 w = wsm[(s * 8 + i) * 512 + c];
                const int kg = kb + 8 + i;
                gemm_kg(A0, w, (const ulonglong2*)hmp[0], kg);
                gemm_kg(A1, w, (const ulonglong2*)hmp[1], kg);
                gemm_kg(A2, w, (const ulonglong2*)hmp[2], kg);
                gemm_kg(A3, w, (const ulonglong2*)hmp[3], kg);
            }
            scrU[s][0][c] = A0; scrU[s][1][c] = A1;
            scrU[s][2][c] = A2; scrU[s][3][c] = A3;
        }
        __syncthreads();

        // mid LSTM update + g_midp store
        {
            const int j = tid & 127, rp = (tid >> 7) & 3, half = tid >> 9;
            const float gi = ((const float*)&scrU[0][rp][j      ])[half] + ((const float*)&scrU[1][rp][j      ])[half];
            const float gf = ((const float*)&scrU[0][rp][j + 128])[half] + ((const float*)&scrU[1][rp][j + 128])[half];
            const float gg = ((const float*)&scrU[0][rp][j + 256])[half] + ((const float*)&scrU[1][rp][j + 256])[half];
            const float go = ((const float*)&scrU[0][rp][j + 384])[half] + ((const float*)&scrU[1][rp][j + 384])[half];
            const float co = ((const float*)&cmp[rp][j])[half];
            const float cn = fsigm(gf) * co + fsigm(gi) * ftanh(gg);
            const float hn = fsigm(go) * ftanh(cn);
            ((float*)&hmp[rp][j])[half] = hn;
            ((float*)&cmp[rp][j])[half] = cn;
            ((float*)&g_midp[((p0 + rp) * TE + t) * NH + j])[half] = hn;
        }
        __syncthreads();
    }

    if (tid < 512) {
        const int rp = tid >> 7, j = tid & 127;
        g_hmp[(p0 + rp) * NH + j] = hmp[rp][j];
        g_cmp[(p0 + rp) * NH + j] = cmp[rp][j];
    }
}

// ---------------- Kernel 4: wx_mid ----------------
__global__ __launch_bounds__(256, 1)
void k_wx(const float* __restrict__ Wx_b)
{
    __shared__ __align__(16) float2 msp[16][128];
    const int tid = threadIdx.x;
    const int ub  = blockIdx.x * 16;

    for (int i = tid; i < 16 * 128; i += 256)
        msp[i >> 7][i & 127] = g_midp[ub * NH + i];
    __syncthreads();

    const int j = tid & 127, rg = tid >> 7;
    const u64 bini = dup2(Wx_b[j]);
    u64 acc[8];
    #pragma unroll
    for (int u = 0; u < 8; ++u) acc[u] = bini;

    #pragma unroll 4
    for (int kg = 0; kg < 32; ++kg) {
        const float4 w = gT4_Wx[kg * 128 + j];
        #pragma unroll
        for (int u = 0; u < 8; ++u)
            gemm_kg(acc[u], w, (const ulonglong2*)msp[rg * 8 + u], kg);
    }
    #pragma unroll
    for (int u = 0; u < 8; ++u) {
        const int gu = ub + rg * 8 + u;
        const int pair = gu / TE, tt = gu % TE;
        const float2 r = unp2(acc[u]);
        g_wx[((2 * pair)     * TE + tt) * NH + j] = r.x;
        g_wx[((2 * pair + 1) * TE + tt) * NH + j] = r.y;
    }
}

// ---------------- Kernel 5: decoder ----------------
__global__ __launch_bounds__(512, 2)
void k_dec(const float* __restrict__ V_w,  const float* __restrict__ V_b,
           const float* __restrict__ dbih, const float* __restrict__ dbhh,
           const float* __restrict__ regw, const float* __restrict__ regb,
           float* __restrict__ out)
{
    __shared__ __align__(16) float2 hicp[2][256];
    __shared__ __align__(16) float2 qsp [2][128];
    __shared__ __align__(16) float2 ssp2[2][TE];
    __shared__ __align__(16) float2 dinp[2][128];
    __shared__ __align__(16) float2 scr [1024];

    const int tid = threadIdx.x;
    const int r0  = blockIdx.x * 4;
    const int p0  = blockIdx.x * 2;
    const int wno = tid >> 5, lane = tid & 31;

    const float4 vw4 = ((const float4*)V_w)[lane];
    const float  vb  = V_b[0];

    {
        const int rp = tid >> 8, k = tid & 255;
        hicp[rp][k] = (k < 128) ? g_hmp[(p0 + rp) * NH + k]
                                : g_cmp[(p0 + rp) * NH + (k - 128)];
    }
    __syncthreads();

    for (int td = 0; td < TD; ++td) {
        {
            const int j = tid & 127, rp = (tid >> 7) & 1, half = tid >> 8;
            u64 acc = 0ull;
            const ulonglong2* hp = (const ulonglong2*)hicp[rp];
            const int k0 = half * 32;
            #pragma unroll 8
            for (int kg = k0; kg < k0 + 32; ++kg)
                gemm_kg(acc, gT4_Wh[kg * 128 + j], hp, kg);
            scr[half * 256 + rp * 128 + j] = unp2(acc);
        }
        __syncthreads();
        if (tid < 256) {
            const int j = tid & 127, rp = tid >> 7;
            const float2 a = scr[rp * 128 + j], b = scr[256 + rp * 128 + j];
            qsp[rp][j] = make_float2(a.x + b.x, a.y + b.y);
        }
        __syncthreads();

        for (int s = wno; s < 4 * TE; s += 16) {
            const int r = s / TE, tt = s % TE;
            const int rp = r >> 1, rh = r & 1;
            const float4 x = ((const float4*)(g_wx + ((r0 + r) * TE + tt) * NH))[lane];
            const float2 q0 = qsp[rp][4 * lane],     q1 = qsp[rp][4 * lane + 1];
            const float2 q2 = qsp[rp][4 * lane + 2], q3 = qsp[rp][4 * lane + 3];
            float acc;
            acc =      ftanh((rh ? q0.y : q0.x) + x.x) * vw4.x;
            acc = fmaf(ftanh((rh ? q1.y : q1.x) + x.y), vw4.y, acc);
            acc = fmaf(ftanh((rh ? q2.y : q2.x) + x.z), vw4.z, acc);
            acc = fmaf(ftanh((rh ? q3.y : q3.x) + x.w), vw4.w, acc);
            #pragma unroll
            for (int o = 16; o; o >>= 1) acc += __shfl_xor_sync(~0u, acc, o);
            if (lane == 0) ((float*)&ssp2[rp][tt])[rh] = acc + vb;
        }
        __syncthreads();

        {
            const int j = tid & 127, rp = (tid >> 7) & 1, half = tid >> 8;
            u64 acc = 0ull;
            const u64* sp = (const u64*)ssp2[rp];
            const float2* mp = g_midp + ((p0 + rp) * TE) * NH + j;
            const int t0 = half * 84;
            #pragma unroll 4
            for (int tt = t0; tt < t0 + 84; ++tt) {
                const u64 m2 = *(const u64*)(mp + tt * NH);
                ffma2(acc, sp[tt], m2);
            }
            scr[half * 256 + rp * 128 + j] = unp2(acc);
        }
        __syncthreads();
        if (tid < 256) {
            const int j = tid & 127, rp = tid >> 7;
            const float2 a = scr[rp * 128 + j], b = scr[256 + rp * 128 + j];
            dinp[rp][j] = make_float2(a.x + b.x, a.y + b.y);
        }
        __syncthreads();

        {
            const int c = tid;
            const u64 bini = dup2(dbih[c] + dbhh[c]);
            u64 A0 = bini, A1 = bini;
            #pragma unroll 4
            for (int kg = 0; kg < 32; ++kg) {
                const float4 w = gT4_dWih[kg * 512 + c];
                gemm_kg(A0, w, (const ulonglong2*)dinp[0], kg);
                gemm_kg(A1, w, (const ulonglong2*)dinp[1], kg);
            }
            #pragma unroll 4
            for (int kg = 0; kg < 32; ++kg) {
                const float4 w = gT4_dWhh[kg * 512 + c];
                gemm_kg(A0, w, (const ulonglong2*)hicp[0], kg);
                gemm_kg(A1, w, (const ulonglong2*)hicp[1], kg);
            }
            scr[c] = unp2(A0); scr[512 + c] = unp2(A1);
        }
        __syncthreads();

        {
            const int j = tid & 127, rp = (tid >> 7) & 1, half = tid >> 8;
            const float gi = ((const float*)&scr[rp * 512 + j      ])[half];
            const float gf = ((const float*)&scr[rp * 512 + j + 128])[half];
            const float gg = ((const float*)&scr[rp * 512 + j + 256])[half];
            const float go = ((const float*)&scr[rp * 512 + j + 384])[half];
            const float co = ((const float*)&hicp[rp][128 + j])[half];
            const float cn = fsigm(gf) * co + fsigm(gi) * ftanh(gg);
            const float hn = fsigm(go) * ftanh(cn);
            ((float*)&hicp[rp][j])[half]       = hn;
            ((float*)&hicp[rp][128 + j])[half] = cn;
        }
        __syncthreads();

        if (wno < 4) {
            const int rp = wno >> 1, rh = wno & 1;
            const float2 h0 = hicp[rp][lane],      h1 = hicp[rp][lane + 32];
            const float2 h2 = hicp[rp][lane + 64], h3 = hicp[rp][lane + 96];
            float acc =       (rh ? h0.y : h0.x) * regw[lane];
            acc = fmaf((rh ? h1.y : h1.x), regw[lane + 32], acc);
            acc = fmaf((rh ? h2.y : h2.x), regw[lane + 64], acc);
            acc = fmaf((rh ? h3.y : h3.x), regw[lane + 96], acc);
            #pragma unroll
            for (int o = 16; o; o >>= 1) acc += __shfl_xor_sync(~0u, acc, o);
            if (lane == 0) out[(r0 + wno) * TD + td] = acc + regb[0];
        }
        __syncthreads();
    }
}

extern "C" void kernel_launch(void* const* d_in, const int* in_sizes, int n_in,
                              void* d_out, int out_size)
{
    const float* X    = (const float*)d_in[0];
    const float* Wi_w = (const float*)d_in[2];
    const float* Wi_b = (const float*)d_in[3];
    const float* We_w = (const float*)d_in[4];
    const float* Vd_w = (const float*)d_in[5];
    const float* Vd_b = (const float*)d_in[6];
    const float* eWih = (const float*)d_in[7];
    const float* eWhh = (const float*)d_in[8];
    const float* ebih = (const float*)d_in[9];
    const float* ebhh = (const float*)d_in[10];
    const float* mWih = (const float*)d_in[11];
    const float* mWhh = (const float*)d_in[12];
    const float* mbih = (const float*)d_in[13];
    const float* mbhh = (const float*)d_in[14];
    const float* Wx_w = (const float*)d_in[15];
    const float* Wx_b = (const float*)d_in[16];
    const float* Wh_w = (const float*)d_in[17];
    const float* V_w  = (const float*)d_in[18];
    const float* V_b  = (const float*)d_in[19];
    const float* dWih = (const float*)d_in[20];
    const float* dWhh = (const float*)d_in[21];
    const float* dbih = (const float*)d_in[22];
    const float* dbhh = (const float*)d_in[23];
    const float* regw = (const float*)d_in[24];
    const float* regb = (const float*)d_in[25];

    cudaFuncSetAttribute(k_enc, cudaFuncAttributeMaxDynamicSharedMemorySize, 163840);
    cudaFuncSetAttribute(k_mid, cudaFuncAttributeMaxDynamicSharedMemorySize, 131072);

    k_tr<<<256, 256>>>(eWih, eWhh, mWih, mWhh, dWih, dWhh,
                       We_w, Wi_w, Vd_w, Wh_w, Wx_w);
    k_enc<<<NB / 8, 1024, 163840>>>(X, Wi_b, Vd_b, ebih, ebhh);
    k_midproj<<<(NB / 2 * TE) / 8, 512>>>(mbih, mbhh);
    k_mid<<<NB / 8, 1024, 131072>>>();
    k_wx<<<(NB / 2 * TE) / 16, 256>>>(Wx_b);
    k_dec<<<NB / 4, 512>>>(V_w, V_b, dbih, dbhh, regw, regb, (float*)d_out);
}